// round 1
// baseline (speedup 1.0000x reference)
#include <cuda_runtime.h>
#include <cuda_bf16.h>
#include <cub/cub.cuh>

// ---------------- problem constants ----------------
#define BB 4
#define AA 10
#define LL 4096
#define NPROP (LL * AA)          // 40960 per batch
#define TOTAL (BB * NPROP)       // 163840
#define PRE_NMS 6000
#define POST_NMS 300
#define NMS_THRESH_F 0.7f
#define MIN_SIZE_F 8.0f
#define FEAT_STRIDE 8
#define CLIP_MAX 32767.0f        // L*FEAT_STRIDE - 1

// ---------------- static device scratch (no allocations allowed) ----------------
__device__ float g_x1[TOTAL];
__device__ float g_x2[TOTAL];
__device__ float g_keys_in[TOTAL];
__device__ float g_keys_out[TOTAL];
__device__ int   g_vals_in[TOTAL];
__device__ int   g_vals_out[TOTAL];
__device__ int   g_seg_off[BB + 1] = {0, NPROP, 2 * NPROP, 3 * NPROP, 4 * NPROP};
__device__ unsigned char g_cub_temp[8 << 20];

__constant__ float c_scales[AA] = {2.f, 4.f, 5.f, 6.f, 8.f, 9.f, 10.f, 12.f, 14.f, 16.f};

// ---------------- kernel 1: decode proposals + scores ----------------
__global__ void compute_props(const float* __restrict__ scores_in,
                              const float* __restrict__ deltas_in) {
    int idx = blockIdx.x * blockDim.x + threadIdx.x;
    if (idx >= TOTAL) return;
    int b = idx / NPROP;
    int r = idx - b * NPROP;   // r = l*A + a
    int l = r / AA;
    int a = r - l * AA;

    // scores_in / twin_deltas shape (B, 2A, L, 1, 1) contiguous
    const int base = b * (2 * AA) * LL;
    float score = scores_in[base + (AA + a) * LL + l];
    float d0    = deltas_in[base + (2 * a) * LL + l];
    float d1    = deltas_in[base + (2 * a + 1) * LL + l];

    float ws   = c_scales[a] * (float)FEAT_STRIDE;
    float ctrA = ((float)FEAT_STRIDE - 1.0f) * 0.5f;      // 3.5
    float shift = (float)(l * FEAT_STRIDE);
    float x1a = ctrA - 0.5f * (ws - 1.0f) + shift;
    float x2a = ctrA + 0.5f * (ws - 1.0f) + shift;

    float width = x2a - x1a + 1.0f;        // == ws (exact)
    float ctr   = x1a + 0.5f * width;

    float pred_ctr = d0 * width + ctr;
    float pred_l   = expf(d1) * width;

    float x1 = pred_ctr - 0.5f * pred_l;
    float x2 = pred_ctr + 0.5f * pred_l;
    x1 = fminf(fmaxf(x1, 0.0f), CLIP_MAX);
    x2 = fminf(fmaxf(x2, 0.0f), CLIP_MAX);

    float ls = x2 - x1 + 1.0f;
    if (ls < MIN_SIZE_F) score = 0.0f;

    g_x1[idx] = x1;
    g_x2[idx] = x2;
    g_keys_in[idx] = score;
    g_vals_in[idx] = r;   // within-batch proposal index
}

// ---------------- kernel 2: per-batch greedy NMS (one block per batch) ----------------
// dynamic smem: sx1[PRE_NMS], sx2[PRE_NMS], kx1[POST_NMS], kx2[POST_NMS]
__global__ void nms_kernel(float* __restrict__ out) {
    extern __shared__ float smem[];
    float* sx1 = smem;
    float* sx2 = sx1 + PRE_NMS;
    float* kx1 = sx2 + PRE_NMS;
    float* kx2 = kx1 + POST_NMS;

    const int b = blockIdx.x;
    const int tid = threadIdx.x;

    // gather top-PRE_NMS proposals (sorted order) into shared
    for (int i = tid; i < PRE_NMS; i += blockDim.x) {
        int gi = b * NPROP + g_vals_out[b * NPROP + i];
        sx1[i] = g_x1[gi];
        sx2[i] = g_x2[gi];
    }
    // init output rows to [b, 0, 0]
    for (int i = tid; i < POST_NMS; i += blockDim.x) {
        float* o = out + (b * POST_NMS + i) * 3;
        o[0] = (float)b;
        o[1] = 0.0f;
        o[2] = 0.0f;
    }
    __syncthreads();

    if (tid < 32) {
        int kept = 0;
        for (int i = 0; i < PRE_NMS && kept < POST_NMS; ++i) {
            float x1 = sx1[i];
            float x2 = sx2[i];
            float len = x2 - x1 + 1.0f;
            bool sup = false;
            for (int j = tid; j < kept; j += 32) {
                float ky1 = kx1[j];
                float ky2 = kx2[j];
                float inter = fminf(x2, ky2) - fmaxf(x1, ky1) + 1.0f;
                inter = fmaxf(inter, 0.0f);
                float uni = len + (ky2 - ky1 + 1.0f) - inter;
                if (inter / uni > NMS_THRESH_F) sup = true;
            }
            if (!__any_sync(0xFFFFFFFFu, sup)) {
                if (tid == 0) {
                    kx1[kept] = x1;
                    kx2[kept] = x2;
                    float* o = out + (b * POST_NMS + kept) * 3;
                    o[1] = x1;
                    o[2] = x2;
                }
                kept++;
                __syncwarp();
            }
        }
    }
}

// ---------------- host launcher ----------------
extern "C" void kernel_launch(void* const* d_in, const int* in_sizes, int n_in,
                              void* d_out, int out_size) {
    (void)in_sizes; (void)n_in; (void)out_size;
    const float* scores = (const float*)d_in[0];
    const float* deltas = (const float*)d_in[1];
    float* out = (float*)d_out;

    float *kin, *kout, *px1; int *vin, *vout, *off; void* tmp;
    cudaGetSymbolAddress((void**)&kin,  g_keys_in);
    cudaGetSymbolAddress((void**)&kout, g_keys_out);
    cudaGetSymbolAddress((void**)&vin,  g_vals_in);
    cudaGetSymbolAddress((void**)&vout, g_vals_out);
    cudaGetSymbolAddress((void**)&off,  g_seg_off);
    cudaGetSymbolAddress((void**)&tmp,  g_cub_temp);
    cudaGetSymbolAddress((void**)&px1,  g_x1);
    (void)px1;

    compute_props<<<(TOTAL + 255) / 256, 256>>>(scores, deltas);

    size_t temp_bytes = sizeof(g_cub_temp);
    cub::DeviceSegmentedRadixSort::SortPairsDescending(
        tmp, temp_bytes,
        kin, kout, vin, vout,
        TOTAL, BB, off, off + 1,
        0, 32, (cudaStream_t)0);

    const int smem_bytes = (2 * PRE_NMS + 2 * POST_NMS) * (int)sizeof(float);
    cudaFuncSetAttribute(nms_kernel, cudaFuncAttributeMaxDynamicSharedMemorySize, smem_bytes);
    nms_kernel<<<BB, 256, smem_bytes>>>(out);
}